// round 12
// baseline (speedup 1.0000x reference)
#include <cuda_runtime.h>
#include <cuda_bf16.h>

#define FULL 0xffffffffu
#define MAXB 4096
#define FDIM 168   // [0:32) accp | [32:64) accc | [64:165) counts | pad

// ---- device scratch (static: no allocation anywhere) ----
__device__ float g_accum[MAXB * FDIM];
__device__ float g_G[FDIM * 64];     // folded weight matrix
__device__ float g_b1[64];           // folded fc1 bias

// ============================================================
// kFold: G[168x64], b1[64] via shared-staged w_fc1.
// f layout: [0:32) u_p | [32:64) u_c | [64:115) cnt_p | [115:165) cnt_c
// G row bases in w_fc1: seg0->64, seg1->96, cnt_p->0, cnt_c->32.
// 11 blocks x 256 thr; block handles 16 G rows; thread = 4 cols.
// ============================================================
__global__ void __launch_bounds__(256)
kfold(const float* __restrict__ w_p2, const float* __restrict__ b_p2,
      const float* __restrict__ w_c2, const float* __restrict__ b_c2,
      const float* __restrict__ emb_gender, const float* __restrict__ emb_korean,
      const float* __restrict__ emb_primary, const float* __restrict__ emb_job,
      const float* __restrict__ emb_rep, const float* __restrict__ emb_place,
      const float* __restrict__ emb_add,
      const float* __restrict__ w_fc1, const float* __restrict__ b_fc1)
{
    __shared__ float ws[128 * 64];   // full w_fc1, 32 KB
    __shared__ float As[16][32];     // this block's 16 A-rows

    const int tid = threadIdx.x;

    // Coalesced full w_fc1 load (2048 float4 / 256 thr = 8 each).
    for (int idx = tid; idx < 128 * 16; idx += 256)
        reinterpret_cast<float4*>(ws)[idx] =
            reinterpret_cast<const float4*>(w_fc1)[idx];

    // Stage A rows: thread (vr, h) loads 2 floats of row v.
    const int vr = tid >> 4;                  // 0..15
    const int v  = blockIdx.x * 16 + vr;
    const int h  = (tid & 15) * 2;
    float a0 = 0.f, a1 = 0.f;
    if (v < 32) {
        a0 = w_p2[v * 32 + h];     a1 = w_p2[v * 32 + h + 1];
    } else if (v < 64) {
        a0 = w_c2[(v - 32) * 32 + h]; a1 = w_c2[(v - 32) * 32 + h + 1];
    } else if (v < 115) {
        const int vv = v - 64;
        const float* er;
        if      (vv < 2)  er = emb_gender  + vv * 32;
        else if (vv < 4)  er = emb_korean  + (vv - 2) * 32;
        else if (vv < 6)  er = emb_primary + (vv - 4) * 32;
        else if (vv < 17) er = emb_job     + (vv - 6) * 32;
        else              er = emb_rep     + (vv - 17) * 32;
        a0 = er[h]; a1 = er[h + 1];
    } else if (v < 165) {
        const int cc = v - 115;
        const float* er = (cc < 19) ? (emb_place + cc * 32)
                                    : (emb_add + (cc - 19) * 32);
        a0 = er[h]; a1 = er[h + 1];
    }                                          // v >= 165: zeros (padding)
    As[vr][h] = a0;
    As[vr][h + 1] = a1;
    __syncthreads();

    // Compute 4 G columns for row v.
    if (v < FDIM) {
        const int wbase = (v < 32) ? 64 : (v < 64) ? 96 : (v < 115) ? 0 : 32;
        const int j0 = (tid & 15) * 4;
        float s0 = 0.f, s1 = 0.f, s2 = 0.f, s3 = 0.f;
        #pragma unroll
        for (int d = 0; d < 32; d++) {
            const float av = As[vr][d];
            const float4 wv = *reinterpret_cast<const float4*>(
                &ws[(wbase + d) * 64 + j0]);
            s0 = fmaf(av, wv.x, s0);
            s1 = fmaf(av, wv.y, s1);
            s2 = fmaf(av, wv.z, s2);
            s3 = fmaf(av, wv.w, s3);
        }
        float4 o = make_float4(s0, s1, s2, s3);
        *reinterpret_cast<float4*>(&g_G[v * 64 + j0]) = o;
    }

    // Folded bias (block 0, threads 0..63).
    if (blockIdx.x == 0 && tid < 64) {
        float s = b_fc1[tid];
        #pragma unroll
        for (int d = 0; d < 32; d++) {
            s = fmaf(b_p2[d], ws[(64 + d) * 64 + tid], s);
            s = fmaf(b_c2[d], ws[(96 + d) * 64 + tid], s);
        }
        g_b1[tid] = s;
    }
}

// ============================================================
// kA: one warp per (row, chunk), RED.ADD into g_accum.
// Count layout (101): gender@0(2) korean@2(2) primary@4(2)
// job@6(11) rep@17(34) place@51(19) add@70(31)
// ============================================================
__device__ __forceinline__ void hupd_g(float* fr, int base, int idx, int lane) {
    unsigned m = __match_any_sync(FULL, idx);
    int leader = __ffs(m) - 1;
    if (lane == leader && idx != 999) {
        atomicAdd(fr + base + idx, (float)__popc(m));
    }
}

__global__ void __launch_bounds__(256)
ka_chunks(const float* __restrict__ cont_p, const float* __restrict__ cont_c,
          const int* __restrict__ cat_p, const int* __restrict__ cat_c,
          const int* __restrict__ lengths,
          const float* __restrict__ w_p1, const float* __restrict__ b_p1,
          const float* __restrict__ w_c1, const float* __restrict__ b_c1,
          int S, int B, int smax)
{
    __shared__ float4 stX[8][32];   // (p0, c0, p1, c1)
    __shared__ float2 stY[8][32];   // (p2, 0)

    const int lane = threadIdx.x & 31;
    const int wib  = threadIdx.x >> 5;
    const int g    = blockIdx.x * 8 + wib;
    const int row  = g / smax;
    const int chunk = g - row * smax;
    if (row >= B) return;

    const int len = lengths[row];
    const int t0  = chunk * 32;
    if (t0 >= len) return;                           // dead chunk: fast exit

    const int nv = min(32, len - t0);
    const bool valid = lane < nv;
    const int rowbase = row * S;
    const int t = t0 + lane;

    float p0 = 0.f, p1 = 0.f, p2 = 0.f, c0 = 0.f, c1 = 0.f;
    int i0 = 999, i1 = 999, i2 = 999, i3 = 999, i4 = 999, j0 = 999, j1 = 999;
    if (valid) {
        const float* cp = cont_p + (rowbase + t) * 3;
        p0 = cp[0]; p1 = cp[1]; p2 = cp[2];
        float2 cc = *reinterpret_cast<const float2*>(cont_c + (rowbase + t) * 2);
        c0 = cc.x; c1 = cc.y;
        const int* ip = cat_p + (rowbase + t) * 5;
        i0 = ip[0]; i1 = ip[1]; i2 = ip[2]; i3 = ip[3]; i4 = ip[4];
        int2 jc = *reinterpret_cast<const int2*>(cat_c + (rowbase + t) * 2);
        j0 = jc.x; j1 = jc.y;
    }

    stX[wib][lane] = make_float4(p0, c0, p1, c1);
    stY[wib][lane] = make_float2(p2, 0.f);

    float* fr = g_accum + row * FDIM;

    hupd_g(fr, 64 +  0, i0, lane);
    hupd_g(fr, 64 +  2, i1, lane);
    hupd_g(fr, 64 +  4, i2, lane);
    hupd_g(fr, 64 +  6, i3, lane);
    hupd_g(fr, 64 + 17, i4, lane);
    hupd_g(fr, 64 + 51, j0, lane);
    hupd_g(fr, 64 + 70, j1, lane);

    const float wp0 = w_p1[lane];
    const float wp1 = w_p1[32 + lane];
    const float wp2 = w_p1[64 + lane];
    const float bp  = b_p1[lane];
    const float wc0 = w_c1[lane];
    const float wc1 = w_c1[32 + lane];
    const float bc  = b_c1[lane];

    __syncwarp();

    float ap0 = 0.f, ap1 = 0.f, ac0 = 0.f, ac1 = 0.f;
    int j = 0;
    #pragma unroll 4
    for (; j + 2 <= nv; j += 2) {
        const float4 xA = stX[wib][j];
        const float2 yA = stY[wib][j];
        const float4 xB = stX[wib][j + 1];
        const float2 yB = stY[wib][j + 1];
        ap0 += fmaxf(fmaf(yA.x, wp2, fmaf(xA.z, wp1, fmaf(xA.x, wp0, bp))), 0.f);
        ac0 += fmaxf(fmaf(xA.w, wc1, fmaf(xA.y, wc0, bc)), 0.f);
        ap1 += fmaxf(fmaf(yB.x, wp2, fmaf(xB.z, wp1, fmaf(xB.x, wp0, bp))), 0.f);
        ac1 += fmaxf(fmaf(xB.w, wc1, fmaf(xB.y, wc0, bc)), 0.f);
    }
    if (j < nv) {
        const float4 xA = stX[wib][j];
        const float2 yA = stY[wib][j];
        ap0 += fmaxf(fmaf(yA.x, wp2, fmaf(xA.z, wp1, fmaf(xA.x, wp0, bp))), 0.f);
        ac0 += fmaxf(fmaf(xA.w, wc1, fmaf(xA.y, wc0, bc)), 0.f);
    }

    atomicAdd(fr + lane,      ap0 + ap1);
    atomicAdd(fr + 32 + lane, ac0 + ac1);
}

// ============================================================
// kC: tiled GEMM epilogue. 32 rows/block, 512 threads (16 warps).
// Thread = 1 row x 4 cols. out = relu(relu(F@G+b1)@w_fc2+b_fc2).
// ============================================================
__global__ void __launch_bounds__(512)
kc_gemm(const int* __restrict__ lengths,
        const float* __restrict__ w_fc2, const float* __restrict__ b_fc2,
        float* __restrict__ out, int B)
{
    __shared__ float Fs[32][FDIM];   // 21504 B
    __shared__ float Gs[84][64];     // 21504 B (two-phase reuse)
    __shared__ float b1s[64];
    __shared__ float il_s[32];

    const int tid  = threadIdx.x;
    const int row0 = blockIdx.x * 32;

    if (tid < 32) {
        const int row = row0 + tid;
        il_s[tid] = (row < B) ? (1.0f / (float)lengths[row]) : 0.f;
    }
    if (tid >= 32 && tid < 96) b1s[tid - 32] = g_b1[tid - 32];
    __syncthreads();   // il_s ready for scaled F load

    // Load F tile with scale-on-load.
    const float4* src = reinterpret_cast<const float4*>(g_accum + (size_t)row0 * FDIM);
    for (int idx = tid; idx < 32 * (FDIM / 4); idx += 512) {
        const int r   = idx / (FDIM / 4);
        const int kk4 = idx - r * (FDIM / 4);
        const int row = row0 + r;
        float4 v = make_float4(0.f, 0.f, 0.f, 0.f);
        if (row < B) v = src[idx];
        const float il = il_s[r];
        const int kb = kk4 * 4;
        const float s0 = (kb + 0 < 64) ? il : ((kb + 0 < 115) ? il * 0.2f : il * 0.5f);
        const float s1 = (kb + 1 < 64) ? il : ((kb + 1 < 115) ? il * 0.2f : il * 0.5f);
        const float s2 = (kb + 2 < 64) ? il : ((kb + 2 < 115) ? il * 0.2f : il * 0.5f);
        const float s3 = (kb + 3 < 64) ? il : ((kb + 3 < 115) ? il * 0.2f : il * 0.5f);
        Fs[r][kb + 0] = v.x * s0;
        Fs[r][kb + 1] = v.y * s1;
        Fs[r][kb + 2] = v.z * s2;
        Fs[r][kb + 3] = v.w * s3;
    }

    // Thread tile: 1 row x 4 cols.
    const int r    = tid >> 4;            // 0..31
    const int colg = tid & 15;            // cols j = colg*4 .. colg*4+3
    const int j0   = colg * 4;

    float a0 = 0.f, a1 = 0.f, a2 = 0.f, a3 = 0.f;

    #pragma unroll
    for (int ph = 0; ph < 2; ph++) {
        __syncthreads();   // ph0: Fs ready; ph1: prior Gs consumers done
        const float4* gsrc = reinterpret_cast<const float4*>(g_G + ph * 84 * 64);
        for (int idx = tid; idx < 84 * 16; idx += 512)
            reinterpret_cast<float4*>(&Gs[0][0])[idx] = gsrc[idx];
        __syncthreads();

        const int kof = ph * 84;
        #pragma unroll 7
        for (int kk = 0; kk < 84; kk++) {
            const float f = Fs[r][kof + kk];
            const float4 gv = *reinterpret_cast<const float4*>(&Gs[kk][j0]);
            a0 = fmaf(f, gv.x, a0);
            a1 = fmaf(f, gv.y, a1);
            a2 = fmaf(f, gv.z, a2);
            a3 = fmaf(f, gv.w, a3);
        }
    }

    // Bias + relu -> H.
    const float h0 = fmaxf(a0 + b1s[j0 + 0], 0.f);
    const float h1 = fmaxf(a1 + b1s[j0 + 1], 0.f);
    const float h2 = fmaxf(a2 + b1s[j0 + 2], 0.f);
    const float h3 = fmaxf(a3 + b1s[j0 + 3], 0.f);

    // fc2 partials: w_fc2 [64][2] row-major; this thread's 4 j's = 8 floats.
    const float4* w2 = reinterpret_cast<const float4*>(w_fc2 + colg * 8);
    const float4 w2a = w2[0];   // (j0o0, j0o1, j1o0, j1o1)
    const float4 w2b = w2[1];   // (j2o0, j2o1, j3o0, j3o1)
    float s0 = h0 * w2a.x + h1 * w2a.z + h2 * w2b.x + h3 * w2b.z;
    float s1 = h0 * w2a.y + h1 * w2a.w + h2 * w2b.y + h3 * w2b.w;

    // Reduce over the 16 col groups (lanes 0-15 within each half-warp).
    #pragma unroll
    for (int m = 1; m <= 8; m <<= 1) {
        s0 += __shfl_xor_sync(FULL, s0, m);
        s1 += __shfl_xor_sync(FULL, s1, m);
    }

    if (colg == 0) {
        const int row = row0 + r;
        if (row < B) {
            float2 o;
            o.x = fmaxf(s0 + b_fc2[0], 0.f);
            o.y = fmaxf(s1 + b_fc2[1], 0.f);
            reinterpret_cast<float2*>(out)[row] = o;
        }
    }
}

extern "C" void kernel_launch(void* const* d_in, const int* in_sizes, int n_in,
                              void* d_out, int out_size)
{
    const float* cont_p   = (const float*)d_in[0];
    const float* cont_c   = (const float*)d_in[1];
    const int*   cat_p    = (const int*)  d_in[2];
    const int*   cat_c    = (const int*)  d_in[3];
    const int*   lengths  = (const int*)  d_in[4];
    const float* w_p1     = (const float*)d_in[5];
    const float* b_p1     = (const float*)d_in[6];
    const float* w_p2     = (const float*)d_in[7];
    const float* b_p2     = (const float*)d_in[8];
    const float* w_c1     = (const float*)d_in[9];
    const float* b_c1     = (const float*)d_in[10];
    const float* w_c2     = (const float*)d_in[11];
    const float* b_c2     = (const float*)d_in[12];
    const float* emb_gender  = (const float*)d_in[13];
    const float* emb_korean  = (const float*)d_in[14];
    const float* emb_primary = (const float*)d_in[15];
    const float* emb_job     = (const float*)d_in[16];
    const float* emb_rep     = (const float*)d_in[17];
    const float* emb_place   = (const float*)d_in[18];
    const float* emb_add     = (const float*)d_in[19];
    const float* w_fc1    = (const float*)d_in[20];
    const float* b_fc1    = (const float*)d_in[21];
    const float* w_fc2    = (const float*)d_in[22];
    const float* b_fc2    = (const float*)d_in[23];
    float* out = (float*)d_out;

    const int B = in_sizes[4];                 // lengths: [B]
    const int S = in_sizes[0] / (B * 3);       // cont_p: [B,S,3]
    const int smax = (S + 31) / 32;            // chunks per row

    // Zero accumulators (graph-capturable async memset, no allocation).
    void* accum_ptr = nullptr;
    cudaGetSymbolAddress(&accum_ptr, g_accum);
    cudaMemsetAsync(accum_ptr, 0, (size_t)B * FDIM * sizeof(float));

    // kFold: build G / b1 (independent of accumulators).
    kfold<<<11, 256>>>(w_p2, b_p2, w_c2, b_c2,
                       emb_gender, emb_korean, emb_primary, emb_job, emb_rep,
                       emb_place, emb_add, w_fc1, b_fc1);

    // kA: one warp per (row, chunk).
    const int chunkBlocks = (B * smax + 7) / 8;
    ka_chunks<<<chunkBlocks, 256>>>(cont_p, cont_c, cat_p, cat_c, lengths,
                                    w_p1, b_p1, w_c1, b_c1, S, B, smax);

    // kC: tiled GEMM epilogue.
    kc_gemm<<<(B + 31) / 32, 512>>>(lengths, w_fc2, b_fc2, out, B);
}